// round 10
// baseline (speedup 1.0000x reference)
#include <cuda_runtime.h>
#include <cstdint>
#include <cstddef>
#include <math_constants.h>

#define BB 4
#define NN 4096
#define CC 64
#define KK 16
#define KWPB 8           // warps per knn block (256 threads, 4 queries/warp)
#define QPW 4            // queries per warp
#define MT 256           // mlp threads per block (8 warps, 4 shared tiles)

// scratch (static device globals: no allocation allowed)
__device__ int g_knn[BB*NN*KK];

// ---- packed f32x2 helpers (FFMA2: only reachable via PTX fma.rn.f32x2) ----
__device__ __forceinline__ unsigned long long pack2(float lo, float hi){
  unsigned long long v;
  asm("mov.b64 %0, {%1,%2};" : "=l"(v) : "f"(lo), "f"(hi));
  return v;
}
__device__ __forceinline__ void unpack2(unsigned long long v, float &lo, float &hi){
  asm("mov.b64 {%0,%1}, %2;" : "=f"(lo), "=f"(hi) : "l"(v));
}
__device__ __forceinline__ unsigned long long ffma2(unsigned long long a,
                                                    unsigned long long b,
                                                    unsigned long long c){
  unsigned long long d;
  asm("fma.rn.f32x2 %0, %1, %2, %3;" : "=l"(d) : "l"(a), "l"(b), "l"(c));
  return d;
}
__device__ __forceinline__ unsigned long long relu2(unsigned long long v){
  float lo, hi; unpack2(v, lo, hi);
  return pack2(fmaxf(lo, 0.f), fmaxf(hi, 0.f));
}

// ============================================================================
// Kernel 1: two-pass warp-per-4-queries exact 16-NN (unchanged from R9).
// ============================================================================
__device__ __forceinline__ void insert_hits(unsigned m, float d, int j0,
                                            float& myD, int& myI, float& worst,
                                            int lane){
  while (m){
    int src = __ffs(m) - 1; m &= m - 1;
    float cd = __shfl_sync(0xffffffffu, d, src);
    if (cd < worst){                                   // warp-uniform recheck
      unsigned em = __ballot_sync(0xffffffffu, (lane < KK) && (myD == worst));
      int leader = __ffs(em) - 1;
      if (lane == leader){ myD = cd; myI = j0 + src; }
      unsigned u = (lane < KK) ? __float_as_uint(myD) : 0u;
      worst = __uint_as_float(__reduce_max_sync(0xffffffffu, u));
    }
  }
}

__global__ __launch_bounds__(KWPB*32) void knn_warp(const float* __restrict__ xyz){
  extern __shared__ float4 s4[];               // 64KB: full point DB of one batch
  const int b = blockIdx.y;
  const float* base = xyz + (size_t)b * NN * 3;
  const int tid = threadIdx.x;
  for (int i = tid; i < NN; i += KWPB*32){
    float px = base[3*i], py = base[3*i+1], pz = base[3*i+2];
    s4[i] = make_float4(px, py, pz, fmaf(px, px, fmaf(py, py, pz*pz)));
  }
  __syncthreads();

  const int wid = tid >> 5, lane = tid & 31;
  const int qbase = (blockIdx.x * KWPB + wid) * QPW;
  const int qblk = qbase & ~31;                // 32-block containing all 4 q's

  float nx[QPW], ny[QPW], nz[QPW], qq[QPW];
  #pragma unroll
  for (int k = 0; k < QPW; k++){
    float4 qv = s4[qbase + k];
    nx[k] = -2.f*qv.x; ny[k] = -2.f*qv.y; nz[k] = -2.f*qv.z; qq[k] = qv.w;
  }

  // ---- pass A: per-lane minimum (self-contamination OK, handled by 17th) ----
  float lmin[QPW];
  #pragma unroll
  for (int k = 0; k < QPW; k++) lmin[k] = CUDART_INF_F;
  #pragma unroll 2
  for (int j0i = 0; j0i < NN; j0i += 32){
    float4 p = s4[j0i + lane];
    #pragma unroll
    for (int k = 0; k < QPW; k++){
      float d = fmaf(nx[k], p.x, fmaf(ny[k], p.y, fmaf(nz[k], p.z, qq[k] + p.w)));
      lmin[k] = fminf(lmin[k], d);
    }
  }

  // ---- tau: 17th smallest of 32 lane minima, then nextafter-up ----
  float tp[QPW];
  #pragma unroll
  for (int k = 0; k < QPW; k++){
    unsigned act = 0xffffffffu, mn = 0;
    const unsigned ub = __float_as_uint(lmin[k]);   // >= 0 -> uint order == float order
    for (int r = 0; r < 17; r++){
      unsigned u = ((act >> lane) & 1u) ? ub : 0x7f800000u;
      mn = __reduce_min_sync(0xffffffffu, u);
      unsigned eq = __ballot_sync(0xffffffffu, u == mn);
      act &= ~(1u << (__ffs(eq) - 1));
    }
    tp[k] = __uint_as_float(mn + 1u);               // strictly > tau >= D[15]
  }

  // ---- pass B: scan with tight sentinels ----
  float myD[QPW]; int myI[QPW]; float worst[QPW];
  #pragma unroll
  for (int k = 0; k < QPW; k++){ myD[k] = tp[k]; myI[k] = 0; worst[k] = tp[k]; }

  #pragma unroll 2
  for (int j0i = 0; j0i < NN; j0i += 32){
    float4 p = s4[j0i + lane];
    float d[QPW]; unsigned m[QPW];
    #pragma unroll
    for (int k = 0; k < QPW; k++){
      d[k] = fmaf(nx[k], p.x, fmaf(ny[k], p.y, fmaf(nz[k], p.z, qq[k] + p.w)));
      m[k] = __ballot_sync(0xffffffffu, d[k] < worst[k]);
    }
    if (j0i == qblk){                          // clear self bits (one iteration)
      #pragma unroll
      for (int k = 0; k < QPW; k++) m[k] &= ~(1u << ((qbase + k) - j0i));
    }
    #pragma unroll
    for (int k = 0; k < QPW; k++)
      if (m[k]) insert_hits(m[k], d[k], j0i, myD[k], myI[k], worst[k], lane);
  }

  if (lane < KK){
    #pragma unroll
    for (int k = 0; k < QPW; k++)
      g_knn[((size_t)b * NN + qbase + k) * KK + lane] = myI[k];
  }
}

// ============================================================================
// Kernel 2: warp-pair tiled register GEMM MLP.
// Two warps share one 64x32 h tile (2 points x 16 nb). Each warp owns 32
// output channels (1/lane): acc = 16 f32x2. smem/CTA = 67KB -> 3 CTAs/SM
// (24 warps/SM vs 16 before). h rows chunk-rotated ((k+row)&7) -> STS.128
// conflict-free phases + 16B broadcast reads. Weight rows XOR-swizzled
// (o ^ (c&31)) -> conflict-free fill AND read.
// ============================================================================
__global__ __launch_bounds__(MT, 3) void mlp_kernel(
    const float* __restrict__ xyz,
    const float* __restrict__ w1,
    const float* __restrict__ w2,
    const float* __restrict__ w3,
    float* __restrict__ out)
{
  extern __shared__ float sm[];
  float* w1s  = sm;              // 256  (64 x (a,b,g,0))
  float* w2T  = sm + 256;        // 4096 swizzled [c_in][c_out ^ (c_in&31)]
  float* w3T  = w2T + 4096;      // 4096
  float* relb = w3T + 4096;      // 4 tiles * 32 * float4 = 512
  float* hb   = relb + 512;      // 4 tiles * 2048 = 8192   -> total 67KB

  const int tid = threadIdx.x, wid = tid >> 5, lane = tid & 31;
  const int tile = wid >> 1, half = wid & 1;
  const int p0 = blockIdx.x * 8 + tile * 2;      // 2 points per tile
  const int b  = p0 >> 12;                       // 8 | NN: no batch straddle
  const int n0 = p0 & (NN - 1);
  const float* xb = xyz + (size_t)b * NN * 3;

  // rel-coords fill (one warp per tile): lane -> m (= pt_local*16 + nb)
  if (half == 0){
    const int pt = p0 + (lane >> 4);
    const int nn = pt & (NN - 1);
    const int ng = g_knn[(size_t)pt * KK + (lane & 15)];
    float4 r4 = make_float4(xb[ng*3+0] - xb[nn*3+0],
                            xb[ng*3+1] - xb[nn*3+1],
                            xb[ng*3+2] - xb[nn*3+2], 0.f);
    *reinterpret_cast<float4*>(relb + tile*128 + lane*4) = r4;
  }

  for (int t = tid; t < 256; t += MT){
    int c = t >> 2, e = t & 3;
    w1s[t] = (e < 3) ? w1[c*3 + e] : 0.f;
  }
  for (int t = tid; t < 4096; t += MT){
    int o = t >> 6, c = t & 63;
    int phys = c*64 + (o ^ (c & 31));
    w2T[phys] = w2[t];
    w3T[phys] = w3[t];
  }
  __syncthreads();

  const int co = half*32 + lane;                 // this lane's output channel
  float* h = hb + tile * 2048;
  const float4* rel4 = reinterpret_cast<const float4*>(relb + tile*128);

  // ---- layer 1: lane computes h row co over m=0..31 ----
  {
    float4 wv = reinterpret_cast<const float4*>(w1s)[co];
    #pragma unroll
    for (int k = 0; k < 8; k++){
      float v[4];
      #pragma unroll
      for (int u = 0; u < 4; u++){
        float4 r = rel4[k*4 + u];
        v[u] = fmaxf(fmaf(wv.x, r.x, fmaf(wv.y, r.y, wv.z*r.z)), 0.f);
      }
      *reinterpret_cast<float4*>(h + co*32 + (((k + co) & 7) << 2)) =
          make_float4(v[0], v[1], v[2], v[3]);
    }
  }
  __syncthreads();

  unsigned long long acc[16];                    // acc[i] = m (2i, 2i+1)

  // ---- layer 2: row co = W2[co] . h ----
  #pragma unroll
  for (int i = 0; i < 16; i++) acc[i] = 0ull;
  #pragma unroll 4
  for (int j = 0; j < CC; j++){
    float w0 = w2T[j*64 + (co ^ (j & 31))];
    unsigned long long wa = pack2(w0, w0);
    const ulonglong2* hrow = reinterpret_cast<const ulonglong2*>(h + j*32);
    #pragma unroll
    for (int k = 0; k < 8; k++){
      ulonglong2 hv = hrow[(k + j) & 7];         // compile-time rotation
      acc[2*k]   = ffma2(wa, hv.x, acc[2*k]);
      acc[2*k+1] = ffma2(wa, hv.y, acc[2*k+1]);
    }
  }
  __syncthreads();                               // all gemm2 reads done

  // relu writeback of row co
  #pragma unroll
  for (int k = 0; k < 8; k++){
    ulonglong2 v;
    v.x = relu2(acc[2*k]); v.y = relu2(acc[2*k+1]);
    *reinterpret_cast<ulonglong2*>(h + co*32 + (((k + co) & 7) << 2)) = v;
  }
  __syncthreads();

  // ---- layer 3 + fused max-pool ----
  #pragma unroll
  for (int i = 0; i < 16; i++) acc[i] = 0ull;
  #pragma unroll 4
  for (int j = 0; j < CC; j++){
    float w0 = w3T[j*64 + (co ^ (j & 31))];
    unsigned long long wa = pack2(w0, w0);
    const ulonglong2* hrow = reinterpret_cast<const ulonglong2*>(h + j*32);
    #pragma unroll
    for (int k = 0; k < 8; k++){
      ulonglong2 hv = hrow[(k + j) & 7];
      acc[2*k]   = ffma2(wa, hv.x, acc[2*k]);
      acc[2*k+1] = ffma2(wa, hv.y, acc[2*k+1]);
    }
  }
  float v0 = -CUDART_INF_F, v1 = -CUDART_INF_F;
  #pragma unroll
  for (int i = 0; i < 8; i++){
    float lo, hi;
    unpack2(acc[i], lo, hi);     v0 = fmaxf(v0, fmaxf(lo, hi));   // m 0..15
    unpack2(acc[8+i], lo, hi);   v1 = fmaxf(v1, fmaxf(lo, hi));   // m 16..31
  }
  float* ob = out + ((size_t)b*CC + co) * NN;
  ob[n0]     = v0;
  ob[n0 + 1] = v1;
}

// ============================================================================
extern "C" void kernel_launch(void* const* d_in, const int* in_sizes, int n_in,
                              void* d_out, int out_size)
{
  const float* xyz = (const float*)d_in[0];
  const float* w1  = (const float*)d_in[1];
  const float* w2  = (const float*)d_in[2];
  const float* w3  = (const float*)d_in[3];
  float* out = (float*)d_out;
  (void)in_sizes; (void)n_in; (void)out_size;

  size_t ksmem = (size_t)NN * sizeof(float4);   // 64KB
  cudaFuncSetAttribute(knn_warp, cudaFuncAttributeMaxDynamicSharedMemorySize, (int)ksmem);
  knn_warp<<<dim3(NN/(QPW*KWPB), BB), KWPB*32, ksmem>>>(xyz);

  size_t msmem = (size_t)(256 + 4096 + 4096 + 512 + 8192) * sizeof(float); // 68608 B
  cudaFuncSetAttribute(mlp_kernel, cudaFuncAttributeMaxDynamicSharedMemorySize, (int)msmem);
  mlp_kernel<<<(BB*NN)/8, MT, msmem>>>(xyz, w1, w2, w3, out);
}